// round 13
// baseline (speedup 1.0000x reference)
#include <cuda_runtime.h>
#include <cstdint>

// ---------------------------------------------------------------------------
// Layer-pipelined cluster LSTM. 8 clusters (batch) x 8 CTAs: ranks 0-3 layer1,
// ranks 4-7 layer2 (each CTA owns 32 units; weights in registers).
// R12/R13: COLUMN-HALF dot split. Each warp owns 32 rows x one 64-col half of
// BOTH weight matrices. The early operand's half-dot (x for L1, h2(s-1) for
// L2) is computed BEFORE the critical wake; only a 64-wide half-dot remains
// after waitc detects the fresh h. Partials stay [row][2]; combine, push
// (st.shared::cluster.v4), aggregated red.add.release arrivals, single
// ld.acquire.u64 polls, split bar.arrive/bar.sync over 4 rotating ids, and
// the depth-4 h ring are unchanged from R11.
// ---------------------------------------------------------------------------

#define H    128
#define NTH  256
#define TENC 168
#define FLEN 168

typedef unsigned long long u64;

// SMEM float offsets
#define OFF_BUF 0                        // replay buffer / X: 169*128
#define OFF_WFC (169*128)                // Wfc, stride 129: 128*129
#define OFF_BFC (OFF_WFC + 128*129)      // bfc: 128
#define OFF_HB  (OFF_BFC + 128)          // 8 slots x 128 (h1:0-3, h2:4-7)
#define OFF_P   (OFF_HB + 1024)          // partials, QUAD-buffered: 4*256
#define OFF_HS  (OFF_P + 1024)           // h stage: 32
#define OFF_SQ  (OFF_HS + 32)            // counters A0,A1,B0,B1 (u32 each)
#define SMEM_FLOATS (OFF_SQ + 4)
#define SMEM_BYTES  (SMEM_FLOATS * 4)

static __device__ __forceinline__ float fast_ex2(float x)
{ float r; asm("ex2.approx.f32 %0,%1;" : "=f"(r) : "f"(x)); return r; }
static __device__ __forceinline__ float fast_rcp(float x)
{ float r; asm("rcp.approx.f32 %0,%1;" : "=f"(r) : "f"(x)); return r; }
static __device__ __forceinline__ float sigf(float x)
{ return fast_rcp(1.0f + fast_ex2(-1.44269504f * x)); }
static __device__ __forceinline__ float tanh_fast(float x)
{ return fmaf(2.0f, sigf(2.0f * x), -1.0f); }

static __device__ __forceinline__ uint32_t s2u(const void *p)
{
    uint32_t a;
    asm("{ .reg .u64 t; cvta.to.shared.u64 t, %1; cvt.u32.u64 %0, t; }"
        : "=r"(a) : "l"(p));
    return a;
}
static __device__ __forceinline__ uint32_t mapa32(uint32_t a, uint32_t r)
{
    uint32_t d;
    asm("mapa.shared::cluster.u32 %0, %1, %2;" : "=r"(d) : "r"(a), "r"(r));
    return d;
}
static __device__ __forceinline__ void stc4(uint32_t a, float4 v)
{
    asm volatile("st.shared::cluster.v4.f32 [%0], {%1,%2,%3,%4};"
                 :: "r"(a), "f"(v.x), "f"(v.y), "f"(v.z), "f"(v.w) : "memory");
}
static __device__ __forceinline__ void red_add_rel(uint32_t a)
{
    asm volatile("red.release.cluster.shared::cluster.add.u32 [%0], %1;"
                 :: "r"(a), "r"(1u) : "memory");
}
static __device__ __forceinline__ u64 ldacq64(uint32_t a)
{
    u64 v;
    asm volatile("ld.acquire.cluster.shared::cta.u64 %0, [%1];"
                 : "=l"(v) : "r"(a) : "memory");
    return v;
}
// Wait until BOTH u32 counters in the pair at addr reach >= n4 (= 4*phase).
static __device__ __forceinline__ void waitc(uint32_t addr, int n4)
{
    if (n4 <= 0) return;
    const uint32_t un = (uint32_t)n4;
    for (;;) {
        u64 v = ldacq64(addr);
        uint32_t m = min((uint32_t)v, (uint32_t)(v >> 32));
        if (m >= un) break;
    }
}

static __device__ __forceinline__ void bar_arrive(uint32_t id)
{ asm volatile("bar.arrive %0, %1;" :: "r"(id), "r"(256u) : "memory"); }
static __device__ __forceinline__ void bar_sync(uint32_t id)
{ asm volatile("bar.sync %0, %1;" :: "r"(id), "r"(256u) : "memory"); }

static __device__ __forceinline__ void fma2(u64 &acc, u64 a, u64 b)
{ asm("fma.rn.f32x2 %0, %1, %2, %0;" : "+l"(acc) : "l"(a), "l"(b)); }
static __device__ __forceinline__ float2 up2(u64 a)
{ float2 r; asm("mov.b64 {%0,%1}, %2;" : "=f"(r.x), "=f"(r.y) : "l"(a)); return r; }

// 64-term half-dot; all lanes read the SAME addresses (pure broadcast).
static __device__ __forceinline__ float dot64b(const u64 *__restrict__ w,
                                               uint32_t base)
{
    u64 a0 = 0, a1 = 0, a2 = 0, a3 = 0;
#pragma unroll
    for (int q = 0; q < 8; q++) {
        uint32_t ad = base + (uint32_t)(q << 5);
        u64 x0, x1, x2, x3;
        asm volatile("ld.shared.v2.u64 {%0,%1},[%2];" : "=l"(x0), "=l"(x1) : "r"(ad));
        asm volatile("ld.shared.v2.u64 {%0,%1},[%2];" : "=l"(x2), "=l"(x3) : "r"(ad + 16));
        fma2(a0, w[4 * q + 0], x0);
        fma2(a1, w[4 * q + 1], x1);
        fma2(a2, w[4 * q + 2], x2);
        fma2(a3, w[4 * q + 3], x3);
    }
    float2 f0 = up2(a0), f1 = up2(a1), f2 = up2(a2), f3 = up2(a3);
    return ((f0.x + f0.y) + (f1.x + f1.y)) + ((f2.x + f2.y) + (f3.x + f3.y));
}

__global__ void __launch_bounds__(NTH, 1) wfm_kernel(
    const float *__restrict__ X,   const float *__restrict__ Wih,
    const float *__restrict__ Whh, const float *__restrict__ bih,
    const float *__restrict__ bhh, const float *__restrict__ Wfc,
    const float *__restrict__ bfc, float *__restrict__ OUT)
{
    extern __shared__ float sm[];
    const int tid  = threadIdx.x;
    const int grp  = blockIdx.x >> 3;
    const int cl   = blockIdx.x & 7;
    const int wrp  = tid >> 5;
    const int lane = tid & 31;
    const int role = cl >> 2;              // 0: layer-1 CTA, 1: layer-2 CTA
    const int base = (cl & 3) * 32;        // owned unit base within H
    const int p    = wrp & 1;              // column half: cols [64p, 64p+64)
    const int rloc = ((wrp >> 1) << 5) + lane;  // local gate row 0..127

    // ---- weights -> registers: row rloc, col half p, BOTH matrices ----
    u64 wx[32], wh[32];                    // wx: Wih rows (x/h1 input);
    {                                      // wh: Whh rows (h recurrent input)
        const int g = rloc >> 5, uu = rloc & 31;
        const int R = role * 512 + g * H + base + uu;
        const u64 *pA = (const u64 *)&Wih[R * H + p * 64];
        const u64 *pB = (const u64 *)&Whh[R * H + p * 64];
#pragma unroll
        for (int i = 0; i < 32; i++) { wx[i] = __ldg(pA + i); wh[i] = __ldg(pB + i); }
    }
    // ---- combine biases (warps 0,1; unit cu = (wrp&1)*16 + lane%16) ----
    const int cu = ((wrp & 1) << 4) + (lane & 15);
    float bi[4];
#pragma unroll
    for (int g2 = 0; g2 < 4; g2++) {
        int R = role * 512 + g2 * H + base + cu;
        bi[g2] = __ldg(&bih[R]) + __ldg(&bhh[R]);
    }

    // ---- SMEM staging ----
    for (int i = tid; i < TENC * H; i += NTH)
        sm[OFF_BUF + i] = __ldg(&X[grp * TENC * H + i]);
    for (int i = tid; i < H * H; i += NTH) {
        int rr = i >> 7, c = i & 127;
        sm[OFF_WFC + rr * 129 + c] = __ldg(&Wfc[i]);
    }
    if (tid < H) sm[OFF_BFC + tid] = __ldg(&bfc[tid]);
    for (int i = tid; i < 1024 + 1024 + 32 + 4; i += NTH)
        sm[OFF_HB + i] = 0.f;                 // HB ring, partials, HS, counters

    const uint32_t sbase = s2u(sm);
    const uint32_t HBA   = sbase + OFF_HB * 4;
    const uint32_t SQA   = sbase + OFF_SQ * 4;    // [A0,A1] pair
    const uint32_t SQB   = SQA + 8;               // [B0,B1] pair
    __syncthreads();
    asm volatile("barrier.cluster.arrive.aligned;" ::: "memory");
    asm volatile("barrier.cluster.wait.aligned;"   ::: "memory");

    // ---- push addresses (warps 0,1; lane<8 -> destination rank = lane) ----
    uint32_t a_hb = 0, a_sq = 0, a_buf = 0;
    if (wrp < 2 && lane < 8) {
        uint32_t br = mapa32(sbase, (uint32_t)lane);
        a_hb  = br + OFF_HB * 4 + (uint32_t)(base + (wrp << 4)) * 4;
        a_sq  = br + OFF_SQ * 4 + (uint32_t)(role * 2 + wrp) * 4;
        a_buf = br + OFF_BUF * 4 + (uint32_t)(base + (wrp << 4)) * 4;
    }

    float cc = 0.f;                     // c-state for unit cu (warps 0,1 lanes<16)
    int s = 0;

    // combine + push (warps 0,1 only; all gating hoisted pre-barrier).
    auto combine_push = [&](int hbslot, int rec) {
        const float *pp = &sm[OFF_P + (s & 3) * 256];
        if (lane < 16) {
            float2 q0 = *(const float2 *)&pp[0 * 64 + cu * 2];
            float2 q1 = *(const float2 *)&pp[1 * 64 + cu * 2];
            float2 q2 = *(const float2 *)&pp[2 * 64 + cu * 2];
            float2 q3 = *(const float2 *)&pp[3 * 64 + cu * 2];
            float gi = q0.x + q0.y + bi[0];
            float gf = q1.x + q1.y + bi[1];
            float gg = q2.x + q2.y + bi[2];
            float go = q3.x + q3.y + bi[3];
            cc = sigf(gf) * cc + sigf(gi) * tanh_fast(gg);
            sm[OFF_HS + cu] = sigf(go) * tanh_fast(cc);
        }
        __syncwarp();
        if (lane < 8) {
            const float4 *hs = (const float4 *)&sm[OFF_HS + ((wrp & 1) << 4)];
            float4 h0 = hs[0], h1 = hs[1], h2 = hs[2], h3 = hs[3];
            uint32_t d = a_hb + (uint32_t)hbslot * 512;
            stc4(d, h0); stc4(d + 16, h1); stc4(d + 32, h2); stc4(d + 48, h3);
            if (rec >= 0 && lane < 4) {
                uint32_t bd = a_buf + (uint32_t)rec * 512;
                stc4(bd, h0); stc4(bd + 16, h1); stc4(bd + 32, h2); stc4(bd + 48, h3);
            }
            red_add_rel(a_sq);
        }
    };

    auto stepL1 = [&](uint32_t xaddr, int bneed) {
        int gate = s - 3;                      // WAR: L2 done reading slot s&3
        if (bneed > gate) gate = bneed;        // + replay-row freshness
        waitc(SQB, 4 * gate);
        // early half: x columns (off critical path)
        float v = dot64b(wx, xaddr + (uint32_t)p * 256);
        // critical half: h1(s-1) columns (only 64-wide after the wake)
        waitc(SQA, 4 * s);
        v += dot64b(wh, HBA + (uint32_t)((s - 1) & 3) * 512 + (uint32_t)p * 256);
        uint32_t sa = sbase + (uint32_t)(OFF_P + (s & 3) * 256 + rloc * 2 + p) * 4;
        asm volatile("st.shared.f32 [%0],%1;" :: "r"(sa), "f"(v) : "memory");
        uint32_t bid = 1 + (s & 3);
        if (wrp < 2) { bar_sync(bid); combine_push(s & 3, -1); }
        else          bar_arrive(bid);
        s++;
    };

    auto stepL2 = [&](int rec) {
        // early half: h2(s-1) columns (one step of slack)
        waitc(SQB, 4 * s);
        float v = dot64b(wh, HBA + (uint32_t)(4 + ((s - 1) & 3)) * 512 + (uint32_t)p * 256);
        // critical half: fresh h1(s) columns
        waitc(SQA, 4 * (s + 1));
        v += dot64b(wx, HBA + (uint32_t)(s & 3) * 512 + (uint32_t)p * 256);
        uint32_t sa = sbase + (uint32_t)(OFF_P + (s & 3) * 256 + rloc * 2 + p) * 4;
        asm volatile("st.shared.f32 [%0],%1;" :: "r"(sa), "f"(v) : "memory");
        uint32_t bid = 1 + (s & 3);
        if (wrp < 2) { bar_sync(bid); combine_push(4 + (s & 3), rec); }
        else          bar_arrive(bid);
        s++;
    };

    if (role == 0) {
        // ---------------- layer-1 pipeline stage ----------------
        for (int t = 0; t < TENC; t++) stepL1(sbase + (uint32_t)t * 512, 0);
        for (int k = 0; k < FLEN; k++) {
            for (int t = 0; t <= k; t++)
                stepL1(sbase + (uint32_t)t * 512,
                       (t < k) ? (s - k + 1) : (k == 0 ? s : 0));
            // forecast FC (redundant across ranks 0-3; rank 0 writes OUT)
            waitc(SQB, 4 * s);                // h2 of last step landed
            const float *hv = &sm[OFF_HB + (4 + ((s - 1) & 3)) * 128];
            const int row = tid >> 1, p2 = tid & 1;
            const float *wr = &sm[OFF_WFC + row * 129 + p2 * 64];
            const float *hq = hv + p2 * 64;
            float a = 0.f;
#pragma unroll
            for (int j = 0; j < 64; j++) a = fmaf(wr[j], hq[j], a);
            a += __shfl_xor_sync(0xffffffffu, a, 1);
            if (p2 == 0) {
                float val = a + sm[OFF_BFC + row];
                sm[OFF_BUF + (k + 1) * H + row] = val;
                if (cl == 0) OUT[(grp * FLEN + k) * H + row] = val;
            }
            __syncthreads();
        }
    } else {
        // ---------------- layer-2 pipeline stage ----------------
        for (int t = 0; t < TENC; t++) stepL2((t == TENC - 1) ? 0 : -1);
        for (int k = 0; k < FLEN; k++)
            for (int t = 0; t <= k; t++) stepL2(t);
    }

    asm volatile("barrier.cluster.arrive.aligned;" ::: "memory");
    asm volatile("barrier.cluster.wait.aligned;"   ::: "memory");
}

extern "C" void kernel_launch(void *const *d_in, const int *in_sizes, int n_in,
                              void *d_out, int out_size)
{
    const float *X   = (const float *)d_in[0];
    const float *Wih = (const float *)d_in[1];
    const float *Whh = (const float *)d_in[2];
    const float *bih = (const float *)d_in[3];
    const float *bhh = (const float *)d_in[4];
    const float *Wfc = (const float *)d_in[5];
    const float *bfc = (const float *)d_in[6];
    float *OUT = (float *)d_out;

    cudaFuncSetAttribute(wfm_kernel,
                         cudaFuncAttributeMaxDynamicSharedMemorySize,
                         SMEM_BYTES);

    cudaLaunchConfig_t cfg = {};
    cfg.gridDim  = {64, 1, 1};
    cfg.blockDim = {NTH, 1, 1};
    cfg.dynamicSmemBytes = SMEM_BYTES;
    cudaLaunchAttribute attrs[1];
    attrs[0].id = cudaLaunchAttributeClusterDimension;
    attrs[0].val.clusterDim = {8, 1, 1};
    cfg.attrs = attrs;
    cfg.numAttrs = 1;

    cudaLaunchKernelEx(&cfg, wfm_kernel, X, Wih, Whh, bih, bhh, Wfc, bfc, OUT);
}

// round 14
// speedup vs baseline: 1.0903x; 1.0903x over previous
#include <cuda_runtime.h>
#include <cstdint>

// ---------------------------------------------------------------------------
// Layer-pipelined cluster LSTM. 8 clusters (batch) x 8 CTAs: ranks 0-3 layer1,
// ranks 4-7 layer2 (each CTA owns 32 units; weights in registers).
// R14 = R11 structure (operand-split dots, one waitc per warp per step) with
// SMSP-aware warp groups: warps 0-3 "early" (x/BUF for L1, h2(s-1) for L2),
// warps 4-7 "critical" (fresh-h operand) -> the post-wake 128-wide dot runs
// on FOUR distinct SMSPs instead of two. Combine warps (0,1) are always in
// the early group. Aggregated red.add.release arrivals, single ld.acquire.u64
// polls, split bar.arrive/bar.sync over 4 rotating ids, depth-4 h ring,
// quad-buffered partials -- all unchanged from R11.
// ---------------------------------------------------------------------------

#define H    128
#define NTH  256
#define TENC 168
#define FLEN 168

typedef unsigned long long u64;

// SMEM float offsets
#define OFF_BUF 0                        // replay buffer / X: 169*128
#define OFF_WFC (169*128)                // Wfc, stride 129: 128*129
#define OFF_BFC (OFF_WFC + 128*129)      // bfc: 128
#define OFF_HB  (OFF_BFC + 128)          // 8 slots x 128 (h1:0-3, h2:4-7)
#define OFF_P   (OFF_HB + 1024)          // partials, QUAD-buffered: 4*256
#define OFF_HS  (OFF_P + 1024)           // h stage: 32
#define OFF_SQ  (OFF_HS + 32)            // counters A0,A1,B0,B1 (u32 each)
#define SMEM_FLOATS (OFF_SQ + 4)
#define SMEM_BYTES  (SMEM_FLOATS * 4)

static __device__ __forceinline__ float fast_ex2(float x)
{ float r; asm("ex2.approx.f32 %0,%1;" : "=f"(r) : "f"(x)); return r; }
static __device__ __forceinline__ float fast_rcp(float x)
{ float r; asm("rcp.approx.f32 %0,%1;" : "=f"(r) : "f"(x)); return r; }
static __device__ __forceinline__ float sigf(float x)
{ return fast_rcp(1.0f + fast_ex2(-1.44269504f * x)); }
static __device__ __forceinline__ float tanh_fast(float x)
{ return fmaf(2.0f, sigf(2.0f * x), -1.0f); }

static __device__ __forceinline__ uint32_t s2u(const void *p)
{
    uint32_t a;
    asm("{ .reg .u64 t; cvta.to.shared.u64 t, %1; cvt.u32.u64 %0, t; }"
        : "=r"(a) : "l"(p));
    return a;
}
static __device__ __forceinline__ uint32_t mapa32(uint32_t a, uint32_t r)
{
    uint32_t d;
    asm("mapa.shared::cluster.u32 %0, %1, %2;" : "=r"(d) : "r"(a), "r"(r));
    return d;
}
static __device__ __forceinline__ void stc4(uint32_t a, float4 v)
{
    asm volatile("st.shared::cluster.v4.f32 [%0], {%1,%2,%3,%4};"
                 :: "r"(a), "f"(v.x), "f"(v.y), "f"(v.z), "f"(v.w) : "memory");
}
static __device__ __forceinline__ void red_add_rel(uint32_t a)
{
    asm volatile("red.release.cluster.shared::cluster.add.u32 [%0], %1;"
                 :: "r"(a), "r"(1u) : "memory");
}
static __device__ __forceinline__ u64 ldacq64(uint32_t a)
{
    u64 v;
    asm volatile("ld.acquire.cluster.shared::cta.u64 %0, [%1];"
                 : "=l"(v) : "r"(a) : "memory");
    return v;
}
// Wait until BOTH u32 counters in the pair at addr reach >= n4 (= 4*phase).
static __device__ __forceinline__ void waitc(uint32_t addr, int n4)
{
    if (n4 <= 0) return;
    const uint32_t un = (uint32_t)n4;
    for (;;) {
        u64 v = ldacq64(addr);
        uint32_t m = min((uint32_t)v, (uint32_t)(v >> 32));
        if (m >= un) break;
    }
}

static __device__ __forceinline__ void bar_arrive(uint32_t id)
{ asm volatile("bar.arrive %0, %1;" :: "r"(id), "r"(256u) : "memory"); }
static __device__ __forceinline__ void bar_sync(uint32_t id)
{ asm volatile("bar.sync %0, %1;" :: "r"(id), "r"(256u) : "memory"); }

static __device__ __forceinline__ void fma2(u64 &acc, u64 a, u64 b)
{ asm("fma.rn.f32x2 %0, %1, %2, %0;" : "+l"(acc) : "l"(a), "l"(b)); }
static __device__ __forceinline__ float2 up2(u64 a)
{ float2 r; asm("mov.b64 {%0,%1}, %2;" : "=f"(r.x), "=f"(r.y) : "l"(a)); return r; }

// 128-term dot; all lanes read the SAME addresses (pure broadcast).
static __device__ __forceinline__ float dot128b(const u64 *__restrict__ w,
                                                uint32_t base)
{
    u64 a0 = 0, a1 = 0, a2 = 0, a3 = 0;
#pragma unroll
    for (int q = 0; q < 16; q++) {
        uint32_t ad = base + (uint32_t)(q << 5);
        u64 x0, x1, x2, x3;
        asm volatile("ld.shared.v2.u64 {%0,%1},[%2];" : "=l"(x0), "=l"(x1) : "r"(ad));
        asm volatile("ld.shared.v2.u64 {%0,%1},[%2];" : "=l"(x2), "=l"(x3) : "r"(ad + 16));
        fma2(a0, w[4 * q + 0], x0);
        fma2(a1, w[4 * q + 1], x1);
        fma2(a2, w[4 * q + 2], x2);
        fma2(a3, w[4 * q + 3], x3);
    }
    float2 f0 = up2(a0), f1 = up2(a1), f2 = up2(a2), f3 = up2(a3);
    return ((f0.x + f0.y) + (f1.x + f1.y)) + ((f2.x + f2.y) + (f3.x + f3.y));
}

__global__ void __launch_bounds__(NTH, 1) wfm_kernel(
    const float *__restrict__ X,   const float *__restrict__ Wih,
    const float *__restrict__ Whh, const float *__restrict__ bih,
    const float *__restrict__ bhh, const float *__restrict__ Wfc,
    const float *__restrict__ bfc, float *__restrict__ OUT)
{
    extern __shared__ float sm[];
    const int tid  = threadIdx.x;
    const int grp  = blockIdx.x >> 3;
    const int cl   = blockIdx.x & 7;
    const int wrp  = tid >> 5;
    const int lane = tid & 31;
    const int role = cl >> 2;              // 0: layer-1 CTA, 1: layer-2 CTA
    const int base = (cl & 3) * 32;        // owned unit base within H
    const int p    = wrp >> 2;             // 0: early group, 1: critical group
    const int rloc = ((wrp & 3) << 5) + lane;   // local gate row 0..127

    // ---- weights -> registers: row rloc, full 128 cols, role-aware pick ----
    // early group (p=0): L1 -> Wih (x input), L2 -> Whh (h2 recurrent)
    // crit group (p=1):  L1 -> Whh (h1(s-1)), L2 -> Wih (fresh h1(s))
    u64 w[64];
    {
        const int g = rloc >> 5, uu = rloc & 31;
        const int R = role * 512 + g * H + base + uu;
        const bool useIh = (role == 0) ? (p == 0) : (p == 1);
        const float *src = useIh ? &Wih[R * H] : &Whh[R * H];
        const u64 *ps = (const u64 *)src;
#pragma unroll
        for (int i = 0; i < 64; i++) w[i] = __ldg(ps + i);
    }
    // ---- combine biases (warps 0,1; unit cu = (wrp&1)*16 + lane%16) ----
    const int cu = ((wrp & 1) << 4) + (lane & 15);
    float bi[4];
#pragma unroll
    for (int g2 = 0; g2 < 4; g2++) {
        int R = role * 512 + g2 * H + base + cu;
        bi[g2] = __ldg(&bih[R]) + __ldg(&bhh[R]);
    }

    // ---- SMEM staging ----
    for (int i = tid; i < TENC * H; i += NTH)
        sm[OFF_BUF + i] = __ldg(&X[grp * TENC * H + i]);
    for (int i = tid; i < H * H; i += NTH) {
        int rr = i >> 7, c = i & 127;
        sm[OFF_WFC + rr * 129 + c] = __ldg(&Wfc[i]);
    }
    if (tid < H) sm[OFF_BFC + tid] = __ldg(&bfc[tid]);
    for (int i = tid; i < 1024 + 1024 + 32 + 4; i += NTH)
        sm[OFF_HB + i] = 0.f;                 // HB ring, partials, HS, counters

    const uint32_t sbase = s2u(sm);
    const uint32_t HBA   = sbase + OFF_HB * 4;
    const uint32_t SQA   = sbase + OFF_SQ * 4;    // [A0,A1] pair
    const uint32_t SQB   = SQA + 8;               // [B0,B1] pair
    __syncthreads();
    asm volatile("barrier.cluster.arrive.aligned;" ::: "memory");
    asm volatile("barrier.cluster.wait.aligned;"   ::: "memory");

    // ---- push addresses (warps 0,1; lane<8 -> destination rank = lane) ----
    uint32_t a_hb = 0, a_sq = 0, a_buf = 0;
    if (wrp < 2 && lane < 8) {
        uint32_t br = mapa32(sbase, (uint32_t)lane);
        a_hb  = br + OFF_HB * 4 + (uint32_t)(base + (wrp << 4)) * 4;
        a_sq  = br + OFF_SQ * 4 + (uint32_t)(role * 2 + wrp) * 4;
        a_buf = br + OFF_BUF * 4 + (uint32_t)(base + (wrp << 4)) * 4;
    }

    float cc = 0.f;                     // c-state for unit cu (warps 0,1 lanes<16)
    int s = 0;

    // combine + push (warps 0,1 only; all gating hoisted pre-barrier).
    auto combine_push = [&](int hbslot, int rec) {
        const float *pp = &sm[OFF_P + (s & 3) * 256];
        if (lane < 16) {
            float2 q0 = *(const float2 *)&pp[0 * 64 + cu * 2];
            float2 q1 = *(const float2 *)&pp[1 * 64 + cu * 2];
            float2 q2 = *(const float2 *)&pp[2 * 64 + cu * 2];
            float2 q3 = *(const float2 *)&pp[3 * 64 + cu * 2];
            float gi = q0.x + q0.y + bi[0];
            float gf = q1.x + q1.y + bi[1];
            float gg = q2.x + q2.y + bi[2];
            float go = q3.x + q3.y + bi[3];
            cc = sigf(gf) * cc + sigf(gi) * tanh_fast(gg);
            sm[OFF_HS + cu] = sigf(go) * tanh_fast(cc);
        }
        __syncwarp();
        if (lane < 8) {
            const float4 *hs = (const float4 *)&sm[OFF_HS + ((wrp & 1) << 4)];
            float4 h0 = hs[0], h1 = hs[1], h2 = hs[2], h3 = hs[3];
            uint32_t d = a_hb + (uint32_t)hbslot * 512;
            stc4(d, h0); stc4(d + 16, h1); stc4(d + 32, h2); stc4(d + 48, h3);
            if (rec >= 0 && lane < 4) {
                uint32_t bd = a_buf + (uint32_t)rec * 512;
                stc4(bd, h0); stc4(bd + 16, h1); stc4(bd + 32, h2); stc4(bd + 48, h3);
            }
            red_add_rel(a_sq);
        }
    };

    auto stepL1 = [&](uint32_t xaddr, int bneed) {
        float v;
        if (p == 0) {                          // early: x dot, off critical path
            int gate = s - 3;                  // WAR: L2 done reading slot s&3
            if (bneed > gate) gate = bneed;    // + replay-row freshness
            waitc(SQB, 4 * gate);
            v = dot128b(w, xaddr);
        } else {                               // critical: h1(s-1), 4 SMSPs
            waitc(SQA, 4 * s);
            v = dot128b(w, HBA + (uint32_t)((s - 1) & 3) * 512);
        }
        uint32_t sa = sbase + (uint32_t)(OFF_P + (s & 3) * 256 + rloc * 2 + p) * 4;
        asm volatile("st.shared.f32 [%0],%1;" :: "r"(sa), "f"(v) : "memory");
        uint32_t bid = 1 + (s & 3);
        if (wrp < 2) { bar_sync(bid); combine_push(s & 3, -1); }
        else          bar_arrive(bid);
        s++;
    };

    auto stepL2 = [&](int rec) {
        float v;
        if (p == 0) {                          // early: h2(s-1) recurrent dot
            waitc(SQB, 4 * s);
            v = dot128b(w, HBA + (uint32_t)(4 + ((s - 1) & 3)) * 512);
        } else {                               // critical: fresh h1(s), 4 SMSPs
            waitc(SQA, 4 * (s + 1));
            v = dot128b(w, HBA + (uint32_t)(s & 3) * 512);
        }
        uint32_t sa = sbase + (uint32_t)(OFF_P + (s & 3) * 256 + rloc * 2 + p) * 4;
        asm volatile("st.shared.f32 [%0],%1;" :: "r"(sa), "f"(v) : "memory");
        uint32_t bid = 1 + (s & 3);
        if (wrp < 2) { bar_sync(bid); combine_push(4 + (s & 3), rec); }
        else          bar_arrive(bid);
        s++;
    };

    if (role == 0) {
        // ---------------- layer-1 pipeline stage ----------------
        for (int t = 0; t < TENC; t++) stepL1(sbase + (uint32_t)t * 512, 0);
        for (int k = 0; k < FLEN; k++) {
            for (int t = 0; t <= k; t++)
                stepL1(sbase + (uint32_t)t * 512,
                       (t < k) ? (s - k + 1) : (k == 0 ? s : 0));
            // forecast FC (redundant across ranks 0-3; rank 0 writes OUT)
            waitc(SQB, 4 * s);                // h2 of last step landed
            const float *hv = &sm[OFF_HB + (4 + ((s - 1) & 3)) * 128];
            const int row = tid >> 1, p2 = tid & 1;
            const float *wr = &sm[OFF_WFC + row * 129 + p2 * 64];
            const float *hq = hv + p2 * 64;
            float a = 0.f;
#pragma unroll
            for (int j = 0; j < 64; j++) a = fmaf(wr[j], hq[j], a);
            a += __shfl_xor_sync(0xffffffffu, a, 1);
            if (p2 == 0) {
                float val = a + sm[OFF_BFC + row];
                sm[OFF_BUF + (k + 1) * H + row] = val;
                if (cl == 0) OUT[(grp * FLEN + k) * H + row] = val;
            }
            __syncthreads();
        }
    } else {
        // ---------------- layer-2 pipeline stage ----------------
        for (int t = 0; t < TENC; t++) stepL2((t == TENC - 1) ? 0 : -1);
        for (int k = 0; k < FLEN; k++)
            for (int t = 0; t <= k; t++) stepL2(t);
    }

    asm volatile("barrier.cluster.arrive.aligned;" ::: "memory");
    asm volatile("barrier.cluster.wait.aligned;"   ::: "memory");
}

extern "C" void kernel_launch(void *const *d_in, const int *in_sizes, int n_in,
                              void *d_out, int out_size)
{
    const float *X   = (const float *)d_in[0];
    const float *Wih = (const float *)d_in[1];
    const float *Whh = (const float *)d_in[2];
    const float *bih = (const float *)d_in[3];
    const float *bhh = (const float *)d_in[4];
    const float *Wfc = (const float *)d_in[5];
    const float *bfc = (const float *)d_in[6];
    float *OUT = (float *)d_out;

    cudaFuncSetAttribute(wfm_kernel,
                         cudaFuncAttributeMaxDynamicSharedMemorySize,
                         SMEM_BYTES);

    cudaLaunchConfig_t cfg = {};
    cfg.gridDim  = {64, 1, 1};
    cfg.blockDim = {NTH, 1, 1};
    cfg.dynamicSmemBytes = SMEM_BYTES;
    cudaLaunchAttribute attrs[1];
    attrs[0].id = cudaLaunchAttributeClusterDimension;
    attrs[0].val.clusterDim = {8, 1, 1};
    cfg.attrs = attrs;
    cfg.numAttrs = 1;

    cudaLaunchKernelEx(&cfg, wfm_kernel, X, Wih, Whh, bih, bhh, Wfc, bfc, OUT);
}